// round 15
// baseline (speedup 1.0000x reference)
#include <cuda_runtime.h>
#include <math.h>

// Problem constants
#define BATCH 4
#define CH    32
#define SEQ   (BATCH*CH)     // 128 independent length-N sequences
#define HH    128            // input H=W
#define P     130            // padded side (128 + 2*1)
#define NTOT  (P*P)          // 16900 = FFT length
#define OCH   32
#define RH    66             // Hermitian-half rows: k1 = 0..65
#define OUTSZ (BATCH*OCH*HH*HH)

#define TWO_PI_F 6.2831853071795864769f

// Scratch (device globals; no allocation allowed)
__device__ float2 g_buf1[SEQ * RH * P];   // Cm (post row-IFFT, rows 1..64 pre-scaled x2)
__device__ float  g_xp[SEQ * NTOT];       // x' (denoised padded image)
__device__ float  g_part[2 * OUTSZ];      // conv partial sums (per channel-half)

// ---------------------------------------------------------------------------
// K_FRONT: fused [zero-pad + col-DFT (cosine-folded) + cross twiddle] +
// [fwd row FFT (radix 13x10) + threshold + inv row FFT + conj cross twiddle
// + Hermitian scale]. TWO sequences per block, processed TOGETHER through
// all row stages (twiddle LDS amortized 2x; 4 syncs in the row phase).
// grid (11, SEQ/2), block 130 (thread = n2/k2), 6 k1 rows per block.
#define R2 6
__global__ void k_front(const float* __restrict__ x) {
    __shared__ float2 Brow[2][R2][P];    // col-DFT result per seq, then X
    __shared__ float2 G[2][R2][P];
    __shared__ float2 tws[P];
    __shared__ float2 w10[10];
    __shared__ __align__(16) float2 twk[R2][64];  // twk[kl][i]=(cos,-sin) for n1=i+1
    const int seq0 = blockIdx.y * 2;
    const int k1_0 = blockIdx.x * R2;
    const int t    = threadIdx.x;        // 0..129

    {
        float s, c;
        sincosf((float)t * (-TWO_PI_F / (float)P), &s, &c);
        tws[t] = make_float2(c, s);
        if (t < 10) {
            sincosf((float)t * (-TWO_PI_F / 10.f), &s, &c);
            w10[t] = make_float2(c, s);
        }
    }
    __syncthreads();
    if (t < 64) {
        #pragma unroll
        for (int kl = 0; kl < R2; kl++) {
            int k1 = k1_0 + kl;
            twk[kl][t] = tws[((t + 1) * k1) % P];   // (cos th, -sin th)
        }
    }
    __syncthreads();

    // Cross twiddle base: Tbase = e^{-2pi i t k1_0 / NTOT}, step St = e^{-2pi i t / NTOT}
    float2 Tbase, St;
    {
        float s, c;
        sincosf((float)(t * k1_0) * (-TWO_PI_F / (float)NTOT), &s, &c);
        Tbase = make_float2(c, s);
        sincosf((float)t * (-TWO_PI_F / (float)NTOT), &s, &c);
        St = make_float2(c, s);
    }

    // ---- Phase 1: column DFT over n1 (cosine-folded), both sequences -------
    {
        float2 acc[2][R2];
        #pragma unroll
        for (int sq = 0; sq < 2; sq++)
            #pragma unroll
            for (int kl = 0; kl < R2; kl++) acc[sq][kl] = make_float2(0.f, 0.f);

        const float* xs0 = x + seq0 * HH * HH;
        const float* xs1 = xs0 + HH * HH;
        const bool interior = (t >= 1 && t <= HH);
        const int col = t - 1;

        for (int i = 0; i < 64; i += 2) {
            float a0  = interior ? __ldg(&xs0[i * HH + col]) : 0.f;
            float b0  = interior ? __ldg(&xs1[i * HH + col]) : 0.f;
            float a0p = (interior && i >= 1) ? __ldg(&xs0[(128 - i) * HH + col]) : 0.f;
            float b0p = (interior && i >= 1) ? __ldg(&xs1[(128 - i) * HH + col]) : 0.f;
            float a1  = interior ? __ldg(&xs0[(i + 1) * HH + col]) : 0.f;
            float b1  = interior ? __ldg(&xs1[(i + 1) * HH + col]) : 0.f;
            float a1p = interior ? __ldg(&xs0[(127 - i) * HH + col]) : 0.f;
            float b1p = interior ? __ldg(&xs1[(127 - i) * HH + col]) : 0.f;

            float ua0 = a0 + a0p, va0 = a0 - a0p;
            float ub0 = b0 + b0p, vb0 = b0 - b0p;
            float ua1 = a1 + a1p, va1 = a1 - a1p;
            float ub1 = b1 + b1p, vb1 = b1 - b1p;

            #pragma unroll
            for (int kl = 0; kl < R2; kl++) {
                float4 tp = *reinterpret_cast<const float4*>(&twk[kl][i]);
                acc[0][kl].x = fmaf(ua0, tp.x, acc[0][kl].x);
                acc[0][kl].y = fmaf(va0, tp.y, acc[0][kl].y);
                acc[0][kl].x = fmaf(ua1, tp.z, acc[0][kl].x);
                acc[0][kl].y = fmaf(va1, tp.w, acc[0][kl].y);
                acc[1][kl].x = fmaf(ub0, tp.x, acc[1][kl].x);
                acc[1][kl].y = fmaf(vb0, tp.y, acc[1][kl].y);
                acc[1][kl].x = fmaf(ub1, tp.z, acc[1][kl].x);
                acc[1][kl].y = fmaf(vb1, tp.w, acc[1][kl].y);
            }
        }

        // n1 = 65 self-pair: contributes x65 * (-1)^k1 to real part
        {
            float e0 = interior ? __ldg(&xs0[64 * HH + col]) : 0.f;
            float e1 = interior ? __ldg(&xs1[64 * HH + col]) : 0.f;
            #pragma unroll
            for (int kl = 0; kl < R2; kl++) {
                float sgn = ((k1_0 + kl) & 1) ? -1.f : 1.f;
                acc[0][kl].x = fmaf(e0, sgn, acc[0][kl].x);
                acc[1][kl].x = fmaf(e1, sgn, acc[1][kl].x);
            }
        }

        float2 T = Tbase;
        #pragma unroll
        for (int kl = 0; kl < R2; kl++) {
            #pragma unroll
            for (int sq = 0; sq < 2; sq++) {
                float2 b;
                b.x = acc[sq][kl].x * T.x - acc[sq][kl].y * T.y;
                b.y = acc[sq][kl].x * T.y + acc[sq][kl].y * T.x;
                Brow[sq][kl][t] = b;
            }
            float2 Tn;
            Tn.x = T.x * St.x - T.y * St.y;
            Tn.y = T.x * St.y + T.y * St.x;
            T = Tn;
        }
    }
    __syncthreads();

    const int bq = t / 10;           // 0..12
    const int rq = t - bq * 10;      // 0..9
    const int r0 = t % 10;

    // ---- fwd stage 1 (both seqs): Brow -> G
    {
        float2 acc[2][R2];
        #pragma unroll
        for (int sq = 0; sq < 2; sq++)
            #pragma unroll
            for (int r = 0; r < R2; r++) acc[sq][r] = make_float2(0.f, 0.f);
        int m = 0;
        #pragma unroll
        for (int a = 0; a < 10; a++) {
            float2 w = w10[m];
            m += rq; if (m >= 10) m -= 10;
            int si = 13 * a + bq;
            #pragma unroll
            for (int sq = 0; sq < 2; sq++)
                #pragma unroll
                for (int r = 0; r < R2; r++) {
                    float2 Bv = Brow[sq][r][si];
                    acc[sq][r].x = fmaf(Bv.x, w.x, acc[sq][r].x);
                    acc[sq][r].x = fmaf(-Bv.y, w.y, acc[sq][r].x);
                    acc[sq][r].y = fmaf(Bv.x, w.y, acc[sq][r].y);
                    acc[sq][r].y = fmaf(Bv.y, w.x, acc[sq][r].y);
                }
        }
        #pragma unroll
        for (int sq = 0; sq < 2; sq++)
            #pragma unroll
            for (int r = 0; r < R2; r++) G[sq][r][t] = acc[sq][r];
    }
    __syncthreads();

    // ---- fwd stage 2 + threshold (both seqs): G -> Brow (X)
    {
        const int k2 = t;
        float2 acc[2][R2];
        #pragma unroll
        for (int sq = 0; sq < 2; sq++)
            #pragma unroll
            for (int r = 0; r < R2; r++) acc[sq][r] = make_float2(0.f, 0.f);
        int idx = 0;
        #pragma unroll
        for (int b = 0; b < 13; b++) {
            float2 tt = tws[idx];
            idx += k2; if (idx >= P) idx -= P;
            int gi = b * 10 + r0;
            #pragma unroll
            for (int sq = 0; sq < 2; sq++)
                #pragma unroll
                for (int r = 0; r < R2; r++) {
                    float2 Gv = G[sq][r][gi];
                    acc[sq][r].x = fmaf(Gv.x, tt.x, acc[sq][r].x);
                    acc[sq][r].x = fmaf(-Gv.y, tt.y, acc[sq][r].x);
                    acc[sq][r].y = fmaf(Gv.x, tt.y, acc[sq][r].y);
                    acc[sq][r].y = fmaf(Gv.y, tt.x, acc[sq][r].y);
                }
        }
        __syncthreads();   // all G reads done before Brow overwrite? (no: Brow!=G) keep for G-read/W below
        #pragma unroll
        for (int sq = 0; sq < 2; sq++)
            #pragma unroll
            for (int r = 0; r < R2; r++) {
                float2 v = acc[sq][r];
                if (fabsf(v.x) < 0.01f) v = make_float2(0.f, 0.f);
                Brow[sq][r][k2] = v;
            }
    }
    __syncthreads();

    // ---- inv stage 1 (conj w10, both seqs): Brow(X) -> G
    {
        float2 acc[2][R2];
        #pragma unroll
        for (int sq = 0; sq < 2; sq++)
            #pragma unroll
            for (int r = 0; r < R2; r++) acc[sq][r] = make_float2(0.f, 0.f);
        int m = 0;
        #pragma unroll
        for (int a = 0; a < 10; a++) {
            float2 w = w10[m];
            m += rq; if (m >= 10) m -= 10;
            int si = 13 * a + bq;
            #pragma unroll
            for (int sq = 0; sq < 2; sq++)
                #pragma unroll
                for (int r = 0; r < R2; r++) {
                    float2 Xv = Brow[sq][r][si];
                    acc[sq][r].x = fmaf(Xv.x, w.x, acc[sq][r].x);
                    acc[sq][r].x = fmaf(Xv.y, w.y, acc[sq][r].x);
                    acc[sq][r].y = fmaf(Xv.y, w.x, acc[sq][r].y);
                    acc[sq][r].y = fmaf(-Xv.x, w.y, acc[sq][r].y);
                }
        }
        #pragma unroll
        for (int sq = 0; sq < 2; sq++)
            #pragma unroll
            for (int r = 0; r < R2; r++) G[sq][r][t] = acc[sq][r];
    }
    __syncthreads();

    // ---- inv stage 2 (conj tws, both seqs) + conj cross twiddle + scale
    {
        const int n2 = t;
        float2 acc[2][R2];
        #pragma unroll
        for (int sq = 0; sq < 2; sq++)
            #pragma unroll
            for (int r = 0; r < R2; r++) acc[sq][r] = make_float2(0.f, 0.f);
        int idx = 0;
        #pragma unroll
        for (int b = 0; b < 13; b++) {
            float2 tt = tws[idx];
            idx += n2; if (idx >= P) idx -= P;
            int gi = b * 10 + r0;
            #pragma unroll
            for (int sq = 0; sq < 2; sq++)
                #pragma unroll
                for (int r = 0; r < R2; r++) {
                    float2 Gv = G[sq][r][gi];
                    acc[sq][r].x = fmaf(Gv.x, tt.x, acc[sq][r].x);
                    acc[sq][r].x = fmaf(Gv.y, tt.y, acc[sq][r].x);
                    acc[sq][r].y = fmaf(Gv.y, tt.x, acc[sq][r].y);
                    acc[sq][r].y = fmaf(-Gv.x, tt.y, acc[sq][r].y);
                }
        }
        float2 T = Tbase;     // T = e^{-2pi i n2 k1 / NTOT}; apply conj(T)
        #pragma unroll
        for (int r = 0; r < R2; r++) {
            int k1 = k1_0 + r;
            float sc = (k1 >= 1 && k1 <= 64) ? 2.0f : 1.0f;
            #pragma unroll
            for (int sq = 0; sq < 2; sq++) {
                float2 cm;
                cm.x = (acc[sq][r].x * T.x + acc[sq][r].y * T.y) * sc;
                cm.y = (acc[sq][r].y * T.x - acc[sq][r].x * T.y) * sc;
                g_buf1[((seq0 + sq) * RH + k1_0 + r) * P + n2] = cm;
            }
            float2 Tn;
            Tn.x = T.x * St.x - T.y * St.y;
            Tn.y = T.x * St.y + T.y * St.x;
            T = Tn;
        }
    }
}

// ---------------------------------------------------------------------------
// K4: inverse column FFT over k1 (folded: 66 terms), real part, scale 1/N.
// TWO sequences per block. grid (10, SEQ/2), block 130, 13 n1 per block.
#define NL4 13
__global__ void k_colifft() {
    __shared__ float2 tws[P];
    __shared__ __align__(16) float2 twk[NL4][RH];   // twk[nl][k1]
    const int seq0 = blockIdx.y * 2;
    const int n1_0 = blockIdx.x * NL4;
    const int n2   = threadIdx.x;

    {
        float s, c;
        sincosf((float)n2 * (-TWO_PI_F / (float)P), &s, &c);
        tws[n2] = make_float2(c, s);
    }
    __syncthreads();
    if (n2 < RH) {
        #pragma unroll
        for (int nl = 0; nl < NL4; nl++) {
            int n1 = n1_0 + nl;
            twk[nl][n2] = tws[(n2 * n1) % P];
        }
    }
    __syncthreads();

    float acc[2][NL4];
    #pragma unroll
    for (int sq = 0; sq < 2; sq++)
        #pragma unroll
        for (int nl = 0; nl < NL4; nl++) acc[sq][nl] = 0.f;

    const float2* Crow0 = g_buf1 + seq0 * RH * P;
    const float2* Crow1 = Crow0 + RH * P;
    for (int k1 = 0; k1 < RH; k1 += 2) {
        float2 a0 = Crow0[k1 * P + n2];
        float2 a1 = Crow0[(k1 + 1) * P + n2];
        float2 b0 = Crow1[k1 * P + n2];
        float2 b1 = Crow1[(k1 + 1) * P + n2];
        #pragma unroll
        for (int nl = 0; nl < NL4; nl++) {
            float4 tp = *reinterpret_cast<const float4*>(&twk[nl][k1]);
            acc[0][nl] = fmaf(a0.x, tp.x, acc[0][nl]);
            acc[0][nl] = fmaf(a0.y, tp.y, acc[0][nl]);
            acc[0][nl] = fmaf(a1.x, tp.z, acc[0][nl]);
            acc[0][nl] = fmaf(a1.y, tp.w, acc[0][nl]);
            acc[1][nl] = fmaf(b0.x, tp.x, acc[1][nl]);
            acc[1][nl] = fmaf(b0.y, tp.y, acc[1][nl]);
            acc[1][nl] = fmaf(b1.x, tp.z, acc[1][nl]);
            acc[1][nl] = fmaf(b1.y, tp.w, acc[1][nl]);
        }
    }

    const float invN = 1.0f / (float)NTOT;
    #pragma unroll
    for (int nl = 0; nl < NL4; nl++) {
        int n1 = n1_0 + nl;
        g_xp[((seq0) * P + n1) * P + n2]     = acc[0][nl] * invN;
        g_xp[((seq0 + 1) * P + n1) * P + n2] = acc[1][nl] * invN;
    }
}

// ---------------------------------------------------------------------------
// K5: 3x3 cross-correlation, 2-pixel blocked, 16ic x 16oc per block.
// DIRECT-LOAD variant: input rows read straight from g_xp via L1/L2
// (no smem staging, no row syncs). Weights in smem (one sync).
// grid (64 row-pairs, 4 b, 4 = chalf*2 + oh), block 128 = (64 tx, 2 ty).
__global__ void __launch_bounds__(128) k_conv(const float* __restrict__ w) {
    __shared__ float wsm[16][9][16];         // [c-local][rs][o-local] (9.2KB)
    const int i0     = blockIdx.x * 2;       // first output row
    const int b      = blockIdx.y;
    const int oh     = blockIdx.z & 1;
    const int chalf  = blockIdx.z >> 1;
    const int c_base = chalf * 16;
    const int tid    = threadIdx.x;
    const int tx     = tid & 63;
    const int ty     = tid >> 6;
    const int j0     = 2 * tx;

    // Preload weights for this (o-half, c-half): 2304 floats
    for (int t = tid; t < 16 * 16 * 9; t += 128) {
        int oo  = t / (16 * 9);
        int rem = t - oo * (16 * 9);
        int cl  = rem / 9;
        int rs  = rem - cl * 9;
        wsm[cl][rs][oo] = w[((oh * 16 + oo) * CH + c_base + cl) * 9 + rs];
    }

    float acc[2][16];                        // [px][oc]
    #pragma unroll
    for (int p = 0; p < 2; p++)
        #pragma unroll
        for (int o = 0; o < 16; o++) acc[p][o] = 0.f;

    __syncthreads();   // weights visible

    // Base pointer to this thread's output row in channel c_base
    const float* xbase = g_xp + ((size_t)(b * CH + c_base)) * NTOT + (i0 + ty) * P;

    #pragma unroll 1
    for (int cl = 0; cl < 16; cl++) {
        const float* gp = xbase + cl * NTOT;
        float xq[3][4];
        #pragma unroll
        for (int r = 0; r < 3; r++) {
            float2 v0 = __ldg(reinterpret_cast<const float2*>(gp + r * P + j0));
            float2 v1 = __ldg(reinterpret_cast<const float2*>(gp + r * P + j0 + 2));
            xq[r][0] = v0.x; xq[r][1] = v0.y; xq[r][2] = v1.x; xq[r][3] = v1.y;
        }

        #pragma unroll
        for (int r = 0; r < 3; r++) {
            #pragma unroll
            for (int s = 0; s < 3; s++) {
                float xv0 = xq[r][s];
                float xv1 = xq[r][s + 1];
                #pragma unroll
                for (int og = 0; og < 4; og++) {
                    float4 w4 = *reinterpret_cast<const float4*>(&wsm[cl][r * 3 + s][og * 4]);
                    acc[0][og * 4 + 0] = fmaf(w4.x, xv0, acc[0][og * 4 + 0]);
                    acc[0][og * 4 + 1] = fmaf(w4.y, xv0, acc[0][og * 4 + 1]);
                    acc[0][og * 4 + 2] = fmaf(w4.z, xv0, acc[0][og * 4 + 2]);
                    acc[0][og * 4 + 3] = fmaf(w4.w, xv0, acc[0][og * 4 + 3]);
                    acc[1][og * 4 + 0] = fmaf(w4.x, xv1, acc[1][og * 4 + 0]);
                    acc[1][og * 4 + 1] = fmaf(w4.y, xv1, acc[1][og * 4 + 1]);
                    acc[1][og * 4 + 2] = fmaf(w4.z, xv1, acc[1][og * 4 + 2]);
                    acc[1][og * 4 + 3] = fmaf(w4.w, xv1, acc[1][og * 4 + 3]);
                }
            }
        }
    }

    float* dst = g_part + chalf * OUTSZ;
    #pragma unroll
    for (int oo = 0; oo < 16; oo++) {
        int o = oh * 16 + oo;
        float2 v = make_float2(acc[0][oo], acc[1][oo]);
        *reinterpret_cast<float2*>(&dst[((b * OCH + o) * HH + (i0 + ty)) * HH + j0]) = v;
    }
}

// ---------------------------------------------------------------------------
// K6: combine 2 partials + bias -> out (one float4 per thread)
__global__ void k_combine(const float* __restrict__ bias, float* __restrict__ out) {
    int idx4 = blockIdx.x * 256 + threadIdx.x;   // OUTSZ/4 = 524288
    int o = (idx4 >> 12) & 31;
    float4 a = *reinterpret_cast<const float4*>(&g_part[4 * idx4]);
    float4 b = *reinterpret_cast<const float4*>(&g_part[OUTSZ + 4 * idx4]);
    float bv = __ldg(&bias[o]);
    float4 r;
    r.x = a.x + b.x + bv;
    r.y = a.y + b.y + bv;
    r.z = a.z + b.z + bv;
    r.w = a.w + b.w + bv;
    *reinterpret_cast<float4*>(&out[4 * idx4]) = r;
}

// ---------------------------------------------------------------------------
extern "C" void kernel_launch(void* const* d_in, const int* in_sizes, int n_in,
                              void* d_out, int out_size) {
    const float* x  = nullptr;
    const float* w  = nullptr;
    const float* bs = nullptr;
    for (int i = 0; i < n_in; i++) {
        if (in_sizes[i] == BATCH * CH * HH * HH)      x  = (const float*)d_in[i];
        else if (in_sizes[i] == OCH * CH * 3 * 3)     w  = (const float*)d_in[i];
        else if (in_sizes[i] == OCH)                  bs = (const float*)d_in[i];
    }
    float* out = (float*)d_out;

    k_front<<<dim3(11, SEQ / 2), P>>>(x);
    k_colifft<<<dim3(10, SEQ / 2), P>>>();
    k_conv<<<dim3(HH / 2, BATCH, 4), 128>>>(w);
    k_combine<<<OUTSZ / 1024, 256>>>(bs, out);
}

// round 16
// speedup vs baseline: 1.1385x; 1.1385x over previous
#include <cuda_runtime.h>
#include <math.h>

// Problem constants
#define BATCH 4
#define CH    32
#define SEQ   (BATCH*CH)     // 128 independent length-N sequences
#define HH    128            // input H=W
#define P     130            // padded side (128 + 2*1)
#define NTOT  (P*P)          // 16900 = FFT length
#define OCH   32
#define RH    66             // Hermitian-half rows: k1 = 0..65
#define OUTSZ (BATCH*OCH*HH*HH)

#define TWO_PI_F 6.2831853071795864769f

// Scratch (device globals; no allocation allowed)
__device__ float2 g_buf1[SEQ * RH * P];   // Cm (post row-IFFT, rows 1..64 pre-scaled x2)
__device__ float  g_xp[SEQ * NTOT];       // x' (denoised padded image)
__device__ float  g_part[2 * OUTSZ];      // conv partial sums (per channel-half)

// ---------------------------------------------------------------------------
// K_FRONT (R14 configuration): fused [zero-pad + col-DFT (cosine-folded) +
// cross twiddle] + [fwd row FFT (radix 13x10) + threshold + inv row FFT +
// conj cross twiddle + Hermitian scale]. TWO sequences/block, row stages
// looped per-seq (G reused).
// grid (11, SEQ/2), block 130 (thread = n2/k2), 6 k1 rows per block.
#define R2 6
__global__ void k_front(const float* __restrict__ x) {
    __shared__ float2 Brow[2][R2][P];    // col-DFT result per seq, then X
    __shared__ float2 G[R2][P];
    __shared__ float2 tws[P];
    __shared__ float2 w10[10];
    __shared__ __align__(16) float2 twk[R2][64];  // twk[kl][i]=(cos,-sin) for n1=i+1
    const int seq0 = blockIdx.y * 2;
    const int k1_0 = blockIdx.x * R2;
    const int t    = threadIdx.x;        // 0..129

    {
        float s, c;
        sincosf((float)t * (-TWO_PI_F / (float)P), &s, &c);
        tws[t] = make_float2(c, s);
        if (t < 10) {
            sincosf((float)t * (-TWO_PI_F / 10.f), &s, &c);
            w10[t] = make_float2(c, s);
        }
    }
    __syncthreads();
    if (t < 64) {
        #pragma unroll
        for (int kl = 0; kl < R2; kl++) {
            int k1 = k1_0 + kl;
            twk[kl][t] = tws[((t + 1) * k1) % P];   // (cos th, -sin th)
        }
    }
    __syncthreads();

    // Cross twiddle base: Tbase = e^{-2pi i t k1_0 / NTOT}, step St = e^{-2pi i t / NTOT}
    float2 Tbase, St;
    {
        float s, c;
        sincosf((float)(t * k1_0) * (-TWO_PI_F / (float)NTOT), &s, &c);
        Tbase = make_float2(c, s);
        sincosf((float)t * (-TWO_PI_F / (float)NTOT), &s, &c);
        St = make_float2(c, s);
    }

    // ---- Phase 1: column DFT over n1 (cosine-folded), both sequences -------
    {
        float2 acc[2][R2];
        #pragma unroll
        for (int sq = 0; sq < 2; sq++)
            #pragma unroll
            for (int kl = 0; kl < R2; kl++) acc[sq][kl] = make_float2(0.f, 0.f);

        const float* xs0 = x + seq0 * HH * HH;
        const float* xs1 = xs0 + HH * HH;
        const bool interior = (t >= 1 && t <= HH);
        const int col = t - 1;

        for (int i = 0; i < 64; i += 2) {
            float a0  = interior ? __ldg(&xs0[i * HH + col]) : 0.f;
            float b0  = interior ? __ldg(&xs1[i * HH + col]) : 0.f;
            float a0p = (interior && i >= 1) ? __ldg(&xs0[(128 - i) * HH + col]) : 0.f;
            float b0p = (interior && i >= 1) ? __ldg(&xs1[(128 - i) * HH + col]) : 0.f;
            float a1  = interior ? __ldg(&xs0[(i + 1) * HH + col]) : 0.f;
            float b1  = interior ? __ldg(&xs1[(i + 1) * HH + col]) : 0.f;
            float a1p = interior ? __ldg(&xs0[(127 - i) * HH + col]) : 0.f;
            float b1p = interior ? __ldg(&xs1[(127 - i) * HH + col]) : 0.f;

            float ua0 = a0 + a0p, va0 = a0 - a0p;
            float ub0 = b0 + b0p, vb0 = b0 - b0p;
            float ua1 = a1 + a1p, va1 = a1 - a1p;
            float ub1 = b1 + b1p, vb1 = b1 - b1p;

            #pragma unroll
            for (int kl = 0; kl < R2; kl++) {
                float4 tp = *reinterpret_cast<const float4*>(&twk[kl][i]);
                acc[0][kl].x = fmaf(ua0, tp.x, acc[0][kl].x);
                acc[0][kl].y = fmaf(va0, tp.y, acc[0][kl].y);
                acc[0][kl].x = fmaf(ua1, tp.z, acc[0][kl].x);
                acc[0][kl].y = fmaf(va1, tp.w, acc[0][kl].y);
                acc[1][kl].x = fmaf(ub0, tp.x, acc[1][kl].x);
                acc[1][kl].y = fmaf(vb0, tp.y, acc[1][kl].y);
                acc[1][kl].x = fmaf(ub1, tp.z, acc[1][kl].x);
                acc[1][kl].y = fmaf(vb1, tp.w, acc[1][kl].y);
            }
        }

        // n1 = 65 self-pair: contributes x65 * (-1)^k1 to real part
        {
            float e0 = interior ? __ldg(&xs0[64 * HH + col]) : 0.f;
            float e1 = interior ? __ldg(&xs1[64 * HH + col]) : 0.f;
            #pragma unroll
            for (int kl = 0; kl < R2; kl++) {
                float sgn = ((k1_0 + kl) & 1) ? -1.f : 1.f;
                acc[0][kl].x = fmaf(e0, sgn, acc[0][kl].x);
                acc[1][kl].x = fmaf(e1, sgn, acc[1][kl].x);
            }
        }

        float2 T = Tbase;
        #pragma unroll
        for (int kl = 0; kl < R2; kl++) {
            #pragma unroll
            for (int sq = 0; sq < 2; sq++) {
                float2 b;
                b.x = acc[sq][kl].x * T.x - acc[sq][kl].y * T.y;
                b.y = acc[sq][kl].x * T.y + acc[sq][kl].y * T.x;
                Brow[sq][kl][t] = b;
            }
            float2 Tn;
            Tn.x = T.x * St.x - T.y * St.y;
            Tn.y = T.x * St.y + T.y * St.x;
            T = Tn;
        }
    }
    __syncthreads();

    const int bq = t / 10;           // 0..12
    const int rq = t - bq * 10;      // 0..9
    const int r0 = t % 10;

    for (int sq = 0; sq < 2; sq++) {
        // ---- fwd stage 1: Brow[sq] -> G
        {
            float2 acc[R2];
            #pragma unroll
            for (int r = 0; r < R2; r++) acc[r] = make_float2(0.f, 0.f);
            int m = 0;
            #pragma unroll
            for (int a = 0; a < 10; a++) {
                float2 w = w10[m];
                m += rq; if (m >= 10) m -= 10;
                int si = 13 * a + bq;
                #pragma unroll
                for (int r = 0; r < R2; r++) {
                    float2 Bv = Brow[sq][r][si];
                    acc[r].x = fmaf(Bv.x, w.x, acc[r].x);
                    acc[r].x = fmaf(-Bv.y, w.y, acc[r].x);
                    acc[r].y = fmaf(Bv.x, w.y, acc[r].y);
                    acc[r].y = fmaf(Bv.y, w.x, acc[r].y);
                }
            }
            __syncthreads();
            #pragma unroll
            for (int r = 0; r < R2; r++) G[r][t] = acc[r];
        }
        __syncthreads();

        // ---- fwd stage 2 + threshold: G -> Brow[sq] (X)
        {
            const int k2 = t;
            float2 acc[R2];
            #pragma unroll
            for (int r = 0; r < R2; r++) acc[r] = make_float2(0.f, 0.f);
            int idx = 0;
            #pragma unroll
            for (int b = 0; b < 13; b++) {
                float2 tt = tws[idx];
                idx += k2; if (idx >= P) idx -= P;
                int gi = b * 10 + r0;
                #pragma unroll
                for (int r = 0; r < R2; r++) {
                    float2 Gv = G[r][gi];
                    acc[r].x = fmaf(Gv.x, tt.x, acc[r].x);
                    acc[r].x = fmaf(-Gv.y, tt.y, acc[r].x);
                    acc[r].y = fmaf(Gv.x, tt.y, acc[r].y);
                    acc[r].y = fmaf(Gv.y, tt.x, acc[r].y);
                }
            }
            __syncthreads();
            #pragma unroll
            for (int r = 0; r < R2; r++) {
                float2 v = acc[r];
                if (fabsf(v.x) < 0.01f) v = make_float2(0.f, 0.f);
                Brow[sq][r][k2] = v;
            }
        }
        __syncthreads();

        // ---- inv stage 1 (conj w10): Brow[sq](X) -> G
        {
            float2 acc[R2];
            #pragma unroll
            for (int r = 0; r < R2; r++) acc[r] = make_float2(0.f, 0.f);
            int m = 0;
            #pragma unroll
            for (int a = 0; a < 10; a++) {
                float2 w = w10[m];
                m += rq; if (m >= 10) m -= 10;
                int si = 13 * a + bq;
                #pragma unroll
                for (int r = 0; r < R2; r++) {
                    float2 Xv = Brow[sq][r][si];
                    acc[r].x = fmaf(Xv.x, w.x, acc[r].x);
                    acc[r].x = fmaf(Xv.y, w.y, acc[r].x);
                    acc[r].y = fmaf(Xv.y, w.x, acc[r].y);
                    acc[r].y = fmaf(-Xv.x, w.y, acc[r].y);
                }
            }
            __syncthreads();
            #pragma unroll
            for (int r = 0; r < R2; r++) G[r][t] = acc[r];
        }
        __syncthreads();

        // ---- inv stage 2 (conj tws) + conj cross twiddle (recurrence) + scale
        {
            const int n2 = t;
            float2 acc[R2];
            #pragma unroll
            for (int r = 0; r < R2; r++) acc[r] = make_float2(0.f, 0.f);
            int idx = 0;
            #pragma unroll
            for (int b = 0; b < 13; b++) {
                float2 tt = tws[idx];
                idx += n2; if (idx >= P) idx -= P;
                int gi = b * 10 + r0;
                #pragma unroll
                for (int r = 0; r < R2; r++) {
                    float2 Gv = G[r][gi];
                    acc[r].x = fmaf(Gv.x, tt.x, acc[r].x);
                    acc[r].x = fmaf(Gv.y, tt.y, acc[r].x);
                    acc[r].y = fmaf(Gv.y, tt.x, acc[r].y);
                    acc[r].y = fmaf(-Gv.x, tt.y, acc[r].y);
                }
            }
            float2* dst = g_buf1 + ((seq0 + sq) * RH + k1_0) * P;
            float2 T = Tbase;     // T = e^{-2pi i n2 k1 / NTOT}; apply conj(T)
            #pragma unroll
            for (int r = 0; r < R2; r++) {
                int k1 = k1_0 + r;
                float sc = (k1 >= 1 && k1 <= 64) ? 2.0f : 1.0f;
                float2 cm;
                cm.x = (acc[r].x * T.x + acc[r].y * T.y) * sc;
                cm.y = (acc[r].y * T.x - acc[r].x * T.y) * sc;
                dst[r * P + n2] = cm;
                float2 Tn;
                Tn.x = T.x * St.x - T.y * St.y;
                Tn.y = T.x * St.y + T.y * St.x;
                T = Tn;
            }
        }
        __syncthreads();   // G reused by next sq
    }
}

// ---------------------------------------------------------------------------
// K4: inverse column FFT over k1 (folded both ways), real part, scale 1/N.
// n1-symmetry fold: cc = sum C.re*cos, ss = sum C.im*(-sin);
// x'[n1] = (cc+ss)/N, x'[130-n1] = (cc-ss)/N. Self-pairs n1=0,65 have ss=0.
// TWO sequences per block. grid (11, SEQ/2), block 130, 6 n1 per block
// (covering n1 = 0..65; partners 65..130 mod 130 written from same thread).
#define NL4F 6
__global__ void k_colifft() {
    __shared__ float2 tws[P];
    __shared__ __align__(16) float2 twk[NL4F][RH];   // twk[nl][k1] = (cos, -sin)
    const int seq0 = blockIdx.y * 2;
    const int n1_0 = blockIdx.x * NL4F;
    const int n2   = threadIdx.x;

    {
        float s, c;
        sincosf((float)n2 * (-TWO_PI_F / (float)P), &s, &c);
        tws[n2] = make_float2(c, s);
    }
    __syncthreads();
    if (n2 < RH) {
        #pragma unroll
        for (int nl = 0; nl < NL4F; nl++) {
            int n1 = n1_0 + nl;
            twk[nl][n2] = tws[(n2 * n1) % P];
        }
    }
    __syncthreads();

    float cc[2][NL4F], ss[2][NL4F];
    #pragma unroll
    for (int sq = 0; sq < 2; sq++)
        #pragma unroll
        for (int nl = 0; nl < NL4F; nl++) { cc[sq][nl] = 0.f; ss[sq][nl] = 0.f; }

    const float2* Crow0 = g_buf1 + seq0 * RH * P;
    const float2* Crow1 = Crow0 + RH * P;
    for (int k1 = 0; k1 < RH; k1 += 2) {
        float2 a0 = Crow0[k1 * P + n2];
        float2 a1 = Crow0[(k1 + 1) * P + n2];
        float2 b0 = Crow1[k1 * P + n2];
        float2 b1 = Crow1[(k1 + 1) * P + n2];
        #pragma unroll
        for (int nl = 0; nl < NL4F; nl++) {
            float4 tp = *reinterpret_cast<const float4*>(&twk[nl][k1]);
            cc[0][nl] = fmaf(a0.x, tp.x, cc[0][nl]);
            ss[0][nl] = fmaf(a0.y, tp.y, ss[0][nl]);
            cc[0][nl] = fmaf(a1.x, tp.z, cc[0][nl]);
            ss[0][nl] = fmaf(a1.y, tp.w, ss[0][nl]);
            cc[1][nl] = fmaf(b0.x, tp.x, cc[1][nl]);
            ss[1][nl] = fmaf(b0.y, tp.y, ss[1][nl]);
            cc[1][nl] = fmaf(b1.x, tp.z, cc[1][nl]);
            ss[1][nl] = fmaf(b1.y, tp.w, ss[1][nl]);
        }
    }

    const float invN = 1.0f / (float)NTOT;
    #pragma unroll
    for (int nl = 0; nl < NL4F; nl++) {
        int n1  = n1_0 + nl;
        int n1m = (P - n1) % P;   // partner row
        #pragma unroll
        for (int sq = 0; sq < 2; sq++) {
            float vp = (cc[sq][nl] + ss[sq][nl]) * invN;
            float vm = (cc[sq][nl] - ss[sq][nl]) * invN;
            g_xp[((seq0 + sq) * P + n1)  * P + n2] = vp;
            g_xp[((seq0 + sq) * P + n1m) * P + n2] = vm;
        }
    }
}

// ---------------------------------------------------------------------------
// K5: 3x3 cross-correlation, 2-pixel blocked, 16ic x 16oc per block.
// MEGA-LOAD (R14): 16 input channels in TWO 8-channel smem batches, 3 syncs.
// grid (64 row-pairs, 4 b, 4 = chalf*2 + oh), block 128 = (64 tx, 2 ty).
__global__ void __launch_bounds__(128) k_conv(const float* __restrict__ w) {
    __shared__ float wsm[16][9][16];         // [c-local][rs][o-local] (9.2KB)
    __shared__ float rows[8][4][132];        // 8 channels x 4 rows (16.9KB)
    const int i0     = blockIdx.x * 2;       // first output row
    const int b      = blockIdx.y;
    const int oh     = blockIdx.z & 1;
    const int chalf  = blockIdx.z >> 1;
    const int c_base = chalf * 16;
    const int tid    = threadIdx.x;
    const int tx     = tid & 63;
    const int ty     = tid >> 6;
    const int j0     = 2 * tx;

    // Preload weights for this (o-half, c-half): 2304 floats
    for (int t = tid; t < 16 * 16 * 9; t += 128) {
        int oo  = t / (16 * 9);
        int rem = t - oo * (16 * 9);
        int cl  = rem / 9;
        int rs  = rem - cl * 9;
        wsm[cl][rs][oo] = w[((oh * 16 + oo) * CH + c_base + cl) * 9 + rs];
    }

    float acc[2][16];                        // [px][oc]
    #pragma unroll
    for (int p = 0; p < 2; p++)
        #pragma unroll
        for (int o = 0; o < 16; o++) acc[p][o] = 0.f;

    for (int g = 0; g < 2; g++) {            // two 8-channel groups
        if (g) __syncthreads();              // protect rows overwrite
        const float* xp0 = g_xp + ((b * CH + c_base + 8 * g) * P + i0) * P;
        for (int t = tid; t < 2080; t += 128) {
            int cc  = t / 260;
            int rem = t - cc * 260;
            int r   = rem / 65;
            int c2  = rem - r * 65;
            float2 v = *reinterpret_cast<const float2*>(xp0 + cc * NTOT + r * P + 2 * c2);
            *reinterpret_cast<float2*>(&rows[cc][r][2 * c2]) = v;
        }
        __syncthreads();

        #pragma unroll
        for (int cc = 0; cc < 8; cc++) {
            const int cl = 8 * g + cc;
            float xq[3][4];
            #pragma unroll
            for (int r = 0; r < 3; r++) {
                float2 a  = *reinterpret_cast<const float2*>(&rows[cc][ty + r][j0]);
                float2 b2 = *reinterpret_cast<const float2*>(&rows[cc][ty + r][j0 + 2]);
                xq[r][0] = a.x; xq[r][1] = a.y; xq[r][2] = b2.x; xq[r][3] = b2.y;
            }

            #pragma unroll
            for (int r = 0; r < 3; r++) {
                #pragma unroll
                for (int s = 0; s < 3; s++) {
                    float xv0 = xq[r][s];
                    float xv1 = xq[r][s + 1];
                    #pragma unroll
                    for (int og = 0; og < 4; og++) {
                        float4 w4 = *reinterpret_cast<const float4*>(&wsm[cl][r * 3 + s][og * 4]);
                        acc[0][og * 4 + 0] = fmaf(w4.x, xv0, acc[0][og * 4 + 0]);
                        acc[0][og * 4 + 1] = fmaf(w4.y, xv0, acc[0][og * 4 + 1]);
                        acc[0][og * 4 + 2] = fmaf(w4.z, xv0, acc[0][og * 4 + 2]);
                        acc[0][og * 4 + 3] = fmaf(w4.w, xv0, acc[0][og * 4 + 3]);
                        acc[1][og * 4 + 0] = fmaf(w4.x, xv1, acc[1][og * 4 + 0]);
                        acc[1][og * 4 + 1] = fmaf(w4.y, xv1, acc[1][og * 4 + 1]);
                        acc[1][og * 4 + 2] = fmaf(w4.z, xv1, acc[1][og * 4 + 2]);
                        acc[1][og * 4 + 3] = fmaf(w4.w, xv1, acc[1][og * 4 + 3]);
                    }
                }
            }
        }
    }

    float* dst = g_part + chalf * OUTSZ;
    #pragma unroll
    for (int oo = 0; oo < 16; oo++) {
        int o = oh * 16 + oo;
        float2 v = make_float2(acc[0][oo], acc[1][oo]);
        *reinterpret_cast<float2*>(&dst[((b * OCH + o) * HH + (i0 + ty)) * HH + j0]) = v;
    }
}

// ---------------------------------------------------------------------------
// K6: combine 2 partials + bias -> out (one float4 per thread)
__global__ void k_combine(const float* __restrict__ bias, float* __restrict__ out) {
    int idx4 = blockIdx.x * 256 + threadIdx.x;   // OUTSZ/4 = 524288
    int o = (idx4 >> 12) & 31;
    float4 a = *reinterpret_cast<const float4*>(&g_part[4 * idx4]);
    float4 b = *reinterpret_cast<const float4*>(&g_part[OUTSZ + 4 * idx4]);
    float bv = __ldg(&bias[o]);
    float4 r;
    r.x = a.x + b.x + bv;
    r.y = a.y + b.y + bv;
    r.z = a.z + b.z + bv;
    r.w = a.w + b.w + bv;
    *reinterpret_cast<float4*>(&out[4 * idx4]) = r;
}

// ---------------------------------------------------------------------------
extern "C" void kernel_launch(void* const* d_in, const int* in_sizes, int n_in,
                              void* d_out, int out_size) {
    const float* x  = nullptr;
    const float* w  = nullptr;
    const float* bs = nullptr;
    for (int i = 0; i < n_in; i++) {
        if (in_sizes[i] == BATCH * CH * HH * HH)      x  = (const float*)d_in[i];
        else if (in_sizes[i] == OCH * CH * 3 * 3)     w  = (const float*)d_in[i];
        else if (in_sizes[i] == OCH)                  bs = (const float*)d_in[i];
    }
    float* out = (float*)d_out;

    k_front<<<dim3(11, SEQ / 2), P>>>(x);
    k_colifft<<<dim3(11, SEQ / 2), P>>>();
    k_conv<<<dim3(HH / 2, BATCH, 4), 128>>>(w);
    k_combine<<<OUTSZ / 1024, 256>>>(bs, out);
}

// round 17
// speedup vs baseline: 1.2179x; 1.0698x over previous
#include <cuda_runtime.h>
#include <math.h>

// Problem constants
#define BATCH 4
#define CH    32
#define SEQ   (BATCH*CH)     // 128 independent length-N sequences
#define HH    128            // input H=W
#define P     130            // padded side (128 + 2*1)
#define NTOT  (P*P)          // 16900 = FFT length
#define OCH   32
#define RH    66             // Hermitian-half rows: k1 = 0..65
#define OUTSZ (BATCH*OCH*HH*HH)

#define TWO_PI_F 6.2831853071795864769f

// Scratch (device globals; no allocation allowed)
__device__ float2 g_buf1[SEQ * RH * P];   // Cm (post row-IFFT, rows 1..64 pre-scaled x2)
__device__ float  g_xp[SEQ * NTOT];       // x' (denoised padded image)
__device__ float  g_part[2 * OUTSZ];      // conv partial sums (per channel-half)

// ---------------------------------------------------------------------------
// K_FRONT: fused [zero-pad + col-DFT (cosine-folded) + cross twiddle] +
// [fwd row FFT (radix 13x10) + threshold + inv row FFT + conj cross twiddle
// + Hermitian scale]. TWO sequences/block, row stages looped per-seq.
// TRANSPOSED row-stage smem ([P][R2]) -> all data LDS/STS are 128-bit.
// Minimal barrier set (pre-write syncs removed where read/write buffers differ).
// grid (11, SEQ/2), block 130 (thread = n2/k2), 6 k1 rows per block.
#define R2 6
__global__ void k_front(const float* __restrict__ x) {
    __shared__ __align__(16) float2 BrowT[2][P][R2];  // [seq][col][row], 12.5KB
    __shared__ __align__(16) float2 Gt[P][R2];        // [col][row], 6.2KB
    __shared__ float2 tws[P];
    __shared__ float2 w10[10];
    __shared__ __align__(16) float2 twk[R2][64];      // (cos,-sin) for n1=i+1
    const int seq0 = blockIdx.y * 2;
    const int k1_0 = blockIdx.x * R2;
    const int t    = threadIdx.x;        // 0..129

    {
        float s, c;
        sincosf((float)t * (-TWO_PI_F / (float)P), &s, &c);
        tws[t] = make_float2(c, s);
        if (t < 10) {
            sincosf((float)t * (-TWO_PI_F / 10.f), &s, &c);
            w10[t] = make_float2(c, s);
        }
    }
    __syncthreads();
    if (t < 64) {
        #pragma unroll
        for (int kl = 0; kl < R2; kl++) {
            int k1 = k1_0 + kl;
            twk[kl][t] = tws[((t + 1) * k1) % P];   // (cos th, -sin th)
        }
    }
    __syncthreads();

    // Cross twiddle base: Tbase = e^{-2pi i t k1_0 / NTOT}, step St = e^{-2pi i t / NTOT}
    float2 Tbase, St;
    {
        float s, c;
        sincosf((float)(t * k1_0) * (-TWO_PI_F / (float)NTOT), &s, &c);
        Tbase = make_float2(c, s);
        sincosf((float)t * (-TWO_PI_F / (float)NTOT), &s, &c);
        St = make_float2(c, s);
    }

    // ---- Phase 1: column DFT over n1 (cosine-folded), both sequences -------
    {
        float2 acc[2][R2];
        #pragma unroll
        for (int sq = 0; sq < 2; sq++)
            #pragma unroll
            for (int kl = 0; kl < R2; kl++) acc[sq][kl] = make_float2(0.f, 0.f);

        const float* xs0 = x + seq0 * HH * HH;
        const float* xs1 = xs0 + HH * HH;
        const bool interior = (t >= 1 && t <= HH);
        const int col = t - 1;

        for (int i = 0; i < 64; i += 2) {
            float a0  = interior ? __ldg(&xs0[i * HH + col]) : 0.f;
            float b0  = interior ? __ldg(&xs1[i * HH + col]) : 0.f;
            float a0p = (interior && i >= 1) ? __ldg(&xs0[(128 - i) * HH + col]) : 0.f;
            float b0p = (interior && i >= 1) ? __ldg(&xs1[(128 - i) * HH + col]) : 0.f;
            float a1  = interior ? __ldg(&xs0[(i + 1) * HH + col]) : 0.f;
            float b1  = interior ? __ldg(&xs1[(i + 1) * HH + col]) : 0.f;
            float a1p = interior ? __ldg(&xs0[(127 - i) * HH + col]) : 0.f;
            float b1p = interior ? __ldg(&xs1[(127 - i) * HH + col]) : 0.f;

            float ua0 = a0 + a0p, va0 = a0 - a0p;
            float ub0 = b0 + b0p, vb0 = b0 - b0p;
            float ua1 = a1 + a1p, va1 = a1 - a1p;
            float ub1 = b1 + b1p, vb1 = b1 - b1p;

            #pragma unroll
            for (int kl = 0; kl < R2; kl++) {
                float4 tp = *reinterpret_cast<const float4*>(&twk[kl][i]);
                acc[0][kl].x = fmaf(ua0, tp.x, acc[0][kl].x);
                acc[0][kl].y = fmaf(va0, tp.y, acc[0][kl].y);
                acc[0][kl].x = fmaf(ua1, tp.z, acc[0][kl].x);
                acc[0][kl].y = fmaf(va1, tp.w, acc[0][kl].y);
                acc[1][kl].x = fmaf(ub0, tp.x, acc[1][kl].x);
                acc[1][kl].y = fmaf(vb0, tp.y, acc[1][kl].y);
                acc[1][kl].x = fmaf(ub1, tp.z, acc[1][kl].x);
                acc[1][kl].y = fmaf(vb1, tp.w, acc[1][kl].y);
            }
        }

        // n1 = 65 self-pair: contributes x65 * (-1)^k1 to real part
        {
            float e0 = interior ? __ldg(&xs0[64 * HH + col]) : 0.f;
            float e1 = interior ? __ldg(&xs1[64 * HH + col]) : 0.f;
            #pragma unroll
            for (int kl = 0; kl < R2; kl++) {
                float sgn = ((k1_0 + kl) & 1) ? -1.f : 1.f;
                acc[0][kl].x = fmaf(e0, sgn, acc[0][kl].x);
                acc[1][kl].x = fmaf(e1, sgn, acc[1][kl].x);
            }
        }

        // Apply cross twiddle, pack into registers, 128-bit stores to BrowT
        float2 bb[2][R2];
        float2 T = Tbase;
        #pragma unroll
        for (int kl = 0; kl < R2; kl++) {
            #pragma unroll
            for (int sq = 0; sq < 2; sq++) {
                bb[sq][kl].x = acc[sq][kl].x * T.x - acc[sq][kl].y * T.y;
                bb[sq][kl].y = acc[sq][kl].x * T.y + acc[sq][kl].y * T.x;
            }
            float2 Tn;
            Tn.x = T.x * St.x - T.y * St.y;
            Tn.y = T.x * St.y + T.y * St.x;
            T = Tn;
        }
        #pragma unroll
        for (int sq = 0; sq < 2; sq++) {
            #pragma unroll
            for (int r = 0; r < R2; r += 2) {
                *reinterpret_cast<float4*>(&BrowT[sq][t][r]) =
                    make_float4(bb[sq][r].x, bb[sq][r].y, bb[sq][r+1].x, bb[sq][r+1].y);
            }
        }
    }
    __syncthreads();

    const int bq = t / 10;           // 0..12
    const int rq = t - bq * 10;      // 0..9
    const int r0 = t % 10;

    for (int sq = 0; sq < 2; sq++) {
        // ---- fwd stage 1: BrowT[sq] -> Gt   (reads Brow, writes G: no pre-sync)
        {
            float2 acc[R2];
            #pragma unroll
            for (int r = 0; r < R2; r++) acc[r] = make_float2(0.f, 0.f);
            int m = 0;
            #pragma unroll
            for (int a = 0; a < 10; a++) {
                float2 w = w10[m];
                m += rq; if (m >= 10) m -= 10;
                int si = 13 * a + bq;
                #pragma unroll
                for (int r = 0; r < R2; r += 2) {
                    float4 q = *reinterpret_cast<const float4*>(&BrowT[sq][si][r]);
                    acc[r].x   = fmaf(q.x, w.x, acc[r].x);
                    acc[r].x   = fmaf(-q.y, w.y, acc[r].x);
                    acc[r].y   = fmaf(q.x, w.y, acc[r].y);
                    acc[r].y   = fmaf(q.y, w.x, acc[r].y);
                    acc[r+1].x = fmaf(q.z, w.x, acc[r+1].x);
                    acc[r+1].x = fmaf(-q.w, w.y, acc[r+1].x);
                    acc[r+1].y = fmaf(q.z, w.y, acc[r+1].y);
                    acc[r+1].y = fmaf(q.w, w.x, acc[r+1].y);
                }
            }
            #pragma unroll
            for (int r = 0; r < R2; r += 2)
                *reinterpret_cast<float4*>(&Gt[t][r]) =
                    make_float4(acc[r].x, acc[r].y, acc[r+1].x, acc[r+1].y);
        }
        __syncthreads();

        // ---- fwd stage 2 + threshold: Gt -> BrowT[sq]  (no pre-sync)
        {
            const int k2 = t;
            float2 acc[R2];
            #pragma unroll
            for (int r = 0; r < R2; r++) acc[r] = make_float2(0.f, 0.f);
            int idx = 0;
            #pragma unroll
            for (int b = 0; b < 13; b++) {
                float2 tt = tws[idx];
                idx += k2; if (idx >= P) idx -= P;
                int gi = b * 10 + r0;
                #pragma unroll
                for (int r = 0; r < R2; r += 2) {
                    float4 q = *reinterpret_cast<const float4*>(&Gt[gi][r]);
                    acc[r].x   = fmaf(q.x, tt.x, acc[r].x);
                    acc[r].x   = fmaf(-q.y, tt.y, acc[r].x);
                    acc[r].y   = fmaf(q.x, tt.y, acc[r].y);
                    acc[r].y   = fmaf(q.y, tt.x, acc[r].y);
                    acc[r+1].x = fmaf(q.z, tt.x, acc[r+1].x);
                    acc[r+1].x = fmaf(-q.w, tt.y, acc[r+1].x);
                    acc[r+1].y = fmaf(q.z, tt.y, acc[r+1].y);
                    acc[r+1].y = fmaf(q.w, tt.x, acc[r+1].y);
                }
            }
            #pragma unroll
            for (int r = 0; r < R2; r++) {
                if (fabsf(acc[r].x) < 0.01f) acc[r] = make_float2(0.f, 0.f);
            }
            #pragma unroll
            for (int r = 0; r < R2; r += 2)
                *reinterpret_cast<float4*>(&BrowT[sq][k2][r]) =
                    make_float4(acc[r].x, acc[r].y, acc[r+1].x, acc[r+1].y);
        }
        __syncthreads();

        // ---- inv stage 1 (conj w10): BrowT[sq] -> Gt  (no pre-sync)
        {
            float2 acc[R2];
            #pragma unroll
            for (int r = 0; r < R2; r++) acc[r] = make_float2(0.f, 0.f);
            int m = 0;
            #pragma unroll
            for (int a = 0; a < 10; a++) {
                float2 w = w10[m];
                m += rq; if (m >= 10) m -= 10;
                int si = 13 * a + bq;
                #pragma unroll
                for (int r = 0; r < R2; r += 2) {
                    float4 q = *reinterpret_cast<const float4*>(&BrowT[sq][si][r]);
                    acc[r].x   = fmaf(q.x, w.x, acc[r].x);
                    acc[r].x   = fmaf(q.y, w.y, acc[r].x);
                    acc[r].y   = fmaf(q.y, w.x, acc[r].y);
                    acc[r].y   = fmaf(-q.x, w.y, acc[r].y);
                    acc[r+1].x = fmaf(q.z, w.x, acc[r+1].x);
                    acc[r+1].x = fmaf(q.w, w.y, acc[r+1].x);
                    acc[r+1].y = fmaf(q.w, w.x, acc[r+1].y);
                    acc[r+1].y = fmaf(-q.z, w.y, acc[r+1].y);
                }
            }
            #pragma unroll
            for (int r = 0; r < R2; r += 2)
                *reinterpret_cast<float4*>(&Gt[t][r]) =
                    make_float4(acc[r].x, acc[r].y, acc[r+1].x, acc[r+1].y);
        }
        __syncthreads();

        // ---- inv stage 2 (conj tws) + conj cross twiddle (recurrence) + scale
        {
            const int n2 = t;
            float2 acc[R2];
            #pragma unroll
            for (int r = 0; r < R2; r++) acc[r] = make_float2(0.f, 0.f);
            int idx = 0;
            #pragma unroll
            for (int b = 0; b < 13; b++) {
                float2 tt = tws[idx];
                idx += n2; if (idx >= P) idx -= P;
                int gi = b * 10 + r0;
                #pragma unroll
                for (int r = 0; r < R2; r += 2) {
                    float4 q = *reinterpret_cast<const float4*>(&Gt[gi][r]);
                    acc[r].x   = fmaf(q.x, tt.x, acc[r].x);
                    acc[r].x   = fmaf(q.y, tt.y, acc[r].x);
                    acc[r].y   = fmaf(q.y, tt.x, acc[r].y);
                    acc[r].y   = fmaf(-q.x, tt.y, acc[r].y);
                    acc[r+1].x = fmaf(q.z, tt.x, acc[r+1].x);
                    acc[r+1].x = fmaf(q.w, tt.y, acc[r+1].x);
                    acc[r+1].y = fmaf(q.w, tt.x, acc[r+1].y);
                    acc[r+1].y = fmaf(-q.z, tt.y, acc[r+1].y);
                }
            }
            float2* dst = g_buf1 + ((seq0 + sq) * RH + k1_0) * P;
            float2 T = Tbase;     // T = e^{-2pi i n2 k1 / NTOT}; apply conj(T)
            #pragma unroll
            for (int r = 0; r < R2; r++) {
                int k1 = k1_0 + r;
                float sc = (k1 >= 1 && k1 <= 64) ? 2.0f : 1.0f;
                float2 cm;
                cm.x = (acc[r].x * T.x + acc[r].y * T.y) * sc;
                cm.y = (acc[r].y * T.x - acc[r].x * T.y) * sc;
                dst[r * P + n2] = cm;
                float2 Tn;
                Tn.x = T.x * St.x - T.y * St.y;
                Tn.y = T.x * St.y + T.y * St.x;
                T = Tn;
            }
        }
        __syncthreads();   // Gt reused by next sq's stage 1
    }
}

// ---------------------------------------------------------------------------
// K4: inverse column FFT over k1 (folded both ways), real part, scale 1/N.
// n1-symmetry fold: cc = sum C.re*cos, ss = sum C.im*(-sin);
// x'[n1] = (cc+ss)/N, x'[130-n1] = (cc-ss)/N. Self-pairs n1=0,65 have ss=0.
// TWO sequences per block. grid (11, SEQ/2), block 130, 6 n1 per block.
#define NL4F 6
__global__ void k_colifft() {
    __shared__ float2 tws[P];
    __shared__ __align__(16) float2 twk[NL4F][RH];   // twk[nl][k1] = (cos, -sin)
    const int seq0 = blockIdx.y * 2;
    const int n1_0 = blockIdx.x * NL4F;
    const int n2   = threadIdx.x;

    {
        float s, c;
        sincosf((float)n2 * (-TWO_PI_F / (float)P), &s, &c);
        tws[n2] = make_float2(c, s);
    }
    __syncthreads();
    if (n2 < RH) {
        #pragma unroll
        for (int nl = 0; nl < NL4F; nl++) {
            int n1 = n1_0 + nl;
            twk[nl][n2] = tws[(n2 * n1) % P];
        }
    }
    __syncthreads();

    float cc[2][NL4F], ss[2][NL4F];
    #pragma unroll
    for (int sq = 0; sq < 2; sq++)
        #pragma unroll
        for (int nl = 0; nl < NL4F; nl++) { cc[sq][nl] = 0.f; ss[sq][nl] = 0.f; }

    const float2* Crow0 = g_buf1 + seq0 * RH * P;
    const float2* Crow1 = Crow0 + RH * P;
    for (int k1 = 0; k1 < RH; k1 += 2) {
        float2 a0 = Crow0[k1 * P + n2];
        float2 a1 = Crow0[(k1 + 1) * P + n2];
        float2 b0 = Crow1[k1 * P + n2];
        float2 b1 = Crow1[(k1 + 1) * P + n2];
        #pragma unroll
        for (int nl = 0; nl < NL4F; nl++) {
            float4 tp = *reinterpret_cast<const float4*>(&twk[nl][k1]);
            cc[0][nl] = fmaf(a0.x, tp.x, cc[0][nl]);
            ss[0][nl] = fmaf(a0.y, tp.y, ss[0][nl]);
            cc[0][nl] = fmaf(a1.x, tp.z, cc[0][nl]);
            ss[0][nl] = fmaf(a1.y, tp.w, ss[0][nl]);
            cc[1][nl] = fmaf(b0.x, tp.x, cc[1][nl]);
            ss[1][nl] = fmaf(b0.y, tp.y, ss[1][nl]);
            cc[1][nl] = fmaf(b1.x, tp.z, cc[1][nl]);
            ss[1][nl] = fmaf(b1.y, tp.w, ss[1][nl]);
        }
    }

    const float invN = 1.0f / (float)NTOT;
    #pragma unroll
    for (int nl = 0; nl < NL4F; nl++) {
        int n1  = n1_0 + nl;
        int n1m = (P - n1) % P;   // partner row
        #pragma unroll
        for (int sq = 0; sq < 2; sq++) {
            float vp = (cc[sq][nl] + ss[sq][nl]) * invN;
            float vm = (cc[sq][nl] - ss[sq][nl]) * invN;
            g_xp[((seq0 + sq) * P + n1)  * P + n2] = vp;
            g_xp[((seq0 + sq) * P + n1m) * P + n2] = vm;
        }
    }
}

// ---------------------------------------------------------------------------
// K5: 3x3 cross-correlation, 2-pixel blocked, 16ic x 16oc per block.
// MEGA-LOAD: 16 input channels in TWO 8-channel smem batches, 3 syncs.
// grid (64 row-pairs, 4 b, 4 = chalf*2 + oh), block 128 = (64 tx, 2 ty).
__global__ void __launch_bounds__(128) k_conv(const float* __restrict__ w) {
    __shared__ float wsm[16][9][16];         // [c-local][rs][o-local] (9.2KB)
    __shared__ float rows[8][4][132];        // 8 channels x 4 rows (16.9KB)
    const int i0     = blockIdx.x * 2;       // first output row
    const int b      = blockIdx.y;
    const int oh     = blockIdx.z & 1;
    const int chalf  = blockIdx.z >> 1;
    const int c_base = chalf * 16;
    const int tid    = threadIdx.x;
    const int tx     = tid & 63;
    const int ty     = tid >> 6;
    const int j0     = 2 * tx;

    // Preload weights for this (o-half, c-half): 2304 floats
    for (int t = tid; t < 16 * 16 * 9; t += 128) {
        int oo  = t / (16 * 9);
        int rem = t - oo * (16 * 9);
        int cl  = rem / 9;
        int rs  = rem - cl * 9;
        wsm[cl][rs][oo] = w[((oh * 16 + oo) * CH + c_base + cl) * 9 + rs];
    }

    float acc[2][16];                        // [px][oc]
    #pragma unroll
    for (int p = 0; p < 2; p++)
        #pragma unroll
        for (int o = 0; o < 16; o++) acc[p][o] = 0.f;

    for (int g = 0; g < 2; g++) {            // two 8-channel groups
        if (g) __syncthreads();              // protect rows overwrite
        const float* xp0 = g_xp + ((b * CH + c_base + 8 * g) * P + i0) * P;
        for (int t = tid; t < 2080; t += 128) {
            int cc  = t / 260;
            int rem = t - cc * 260;
            int r   = rem / 65;
            int c2  = rem - r * 65;
            float2 v = *reinterpret_cast<const float2*>(xp0 + cc * NTOT + r * P + 2 * c2);
            *reinterpret_cast<float2*>(&rows[cc][r][2 * c2]) = v;
        }
        __syncthreads();

        #pragma unroll
        for (int cc = 0; cc < 8; cc++) {
            const int cl = 8 * g + cc;
            float xq[3][4];
            #pragma unroll
            for (int r = 0; r < 3; r++) {
                float2 a  = *reinterpret_cast<const float2*>(&rows[cc][ty + r][j0]);
                float2 b2 = *reinterpret_cast<const float2*>(&rows[cc][ty + r][j0 + 2]);
                xq[r][0] = a.x; xq[r][1] = a.y; xq[r][2] = b2.x; xq[r][3] = b2.y;
            }

            #pragma unroll
            for (int r = 0; r < 3; r++) {
                #pragma unroll
                for (int s = 0; s < 3; s++) {
                    float xv0 = xq[r][s];
                    float xv1 = xq[r][s + 1];
                    #pragma unroll
                    for (int og = 0; og < 4; og++) {
                        float4 w4 = *reinterpret_cast<const float4*>(&wsm[cl][r * 3 + s][og * 4]);
                        acc[0][og * 4 + 0] = fmaf(w4.x, xv0, acc[0][og * 4 + 0]);
                        acc[0][og * 4 + 1] = fmaf(w4.y, xv0, acc[0][og * 4 + 1]);
                        acc[0][og * 4 + 2] = fmaf(w4.z, xv0, acc[0][og * 4 + 2]);
                        acc[0][og * 4 + 3] = fmaf(w4.w, xv0, acc[0][og * 4 + 3]);
                        acc[1][og * 4 + 0] = fmaf(w4.x, xv1, acc[1][og * 4 + 0]);
                        acc[1][og * 4 + 1] = fmaf(w4.y, xv1, acc[1][og * 4 + 1]);
                        acc[1][og * 4 + 2] = fmaf(w4.z, xv1, acc[1][og * 4 + 2]);
                        acc[1][og * 4 + 3] = fmaf(w4.w, xv1, acc[1][og * 4 + 3]);
                    }
                }
            }
        }
    }

    float* dst = g_part + chalf * OUTSZ;
    #pragma unroll
    for (int oo = 0; oo < 16; oo++) {
        int o = oh * 16 + oo;
        float2 v = make_float2(acc[0][oo], acc[1][oo]);
        *reinterpret_cast<float2*>(&dst[((b * OCH + o) * HH + (i0 + ty)) * HH + j0]) = v;
    }
}

// ---------------------------------------------------------------------------
// K6: combine 2 partials + bias -> out (one float4 per thread)
__global__ void k_combine(const float* __restrict__ bias, float* __restrict__ out) {
    int idx4 = blockIdx.x * 256 + threadIdx.x;   // OUTSZ/4 = 524288
    int o = (idx4 >> 12) & 31;
    float4 a = *reinterpret_cast<const float4*>(&g_part[4 * idx4]);
    float4 b = *reinterpret_cast<const float4*>(&g_part[OUTSZ + 4 * idx4]);
    float bv = __ldg(&bias[o]);
    float4 r;
    r.x = a.x + b.x + bv;
    r.y = a.y + b.y + bv;
    r.z = a.z + b.z + bv;
    r.w = a.w + b.w + bv;
    *reinterpret_cast<float4*>(&out[4 * idx4]) = r;
}

// ---------------------------------------------------------------------------
extern "C" void kernel_launch(void* const* d_in, const int* in_sizes, int n_in,
                              void* d_out, int out_size) {
    const float* x  = nullptr;
    const float* w  = nullptr;
    const float* bs = nullptr;
    for (int i = 0; i < n_in; i++) {
        if (in_sizes[i] == BATCH * CH * HH * HH)      x  = (const float*)d_in[i];
        else if (in_sizes[i] == OCH * CH * 3 * 3)     w  = (const float*)d_in[i];
        else if (in_sizes[i] == OCH)                  bs = (const float*)d_in[i];
    }
    float* out = (float*)d_out;

    k_front<<<dim3(11, SEQ / 2), P>>>(x);
    k_colifft<<<dim3(11, SEQ / 2), P>>>();
    k_conv<<<dim3(HH / 2, BATCH, 4), 128>>>(w);
    k_combine<<<OUTSZ / 1024, 256>>>(bs, out);
}